// round 10
// baseline (speedup 1.0000x reference)
#include <cuda_runtime.h>
#include <cstdint>

#define NN 100000
#define NE 1600000
#define C  128

#define GEMM_BLOCKS  ((NN + 127) / 128)    // 782
#define COUNT_BLOCKS ((NE + 255) / 256)    // 6250

#define SCAN_CHUNK 1024
#define NBLK_SCAN ((NN + SCAN_CHUNK - 1) / SCAN_CHUNK)   // 98

// ---------------------------------------------------------------------------
// Scratch (device globals — no allocation allowed)
// ---------------------------------------------------------------------------
__device__ int   g_cnt [NN];
__device__ int   g_off [NN + 1];
__device__ int   g_bsum[SCAN_CHUNK];
__device__ int   g_csrc[NE];
__device__ float g_dinv[NN];
__device__ float g_h   [(size_t)NN * C];   // x@W1 (fp32)
__device__ float g_hn  [(size_t)NN * C];   // normalized hidden (fp32)

__device__ __forceinline__ uint32_t f2tf32(float f) {
    uint32_t r; asm("cvt.rna.tf32.f32 %0, %1;" : "=r"(r) : "f"(f)); return r;
}

// ---------------------------------------------------------------------------
// CSR build pieces
// ---------------------------------------------------------------------------
__global__ void zero_cnt_kernel() {
    int i = blockIdx.x * blockDim.x + threadIdx.x;
    if (i < NN) g_cnt[i] = 0;
}
__global__ __launch_bounds__(SCAN_CHUNK)
void scan1_kernel() {
    __shared__ int sh[SCAN_CHUNK];
    int i = blockIdx.x * SCAN_CHUNK + threadIdx.x;
    int v = (i < NN) ? g_cnt[i] : 0;
    sh[threadIdx.x] = v;
    __syncthreads();
#pragma unroll
    for (int off = 1; off < SCAN_CHUNK; off <<= 1) {
        int t = (threadIdx.x >= off) ? sh[threadIdx.x - off] : 0;
        __syncthreads();
        sh[threadIdx.x] += t;
        __syncthreads();
    }
    if (i < NN) g_off[i] = sh[threadIdx.x] - v;   // exclusive within block
    if (threadIdx.x == SCAN_CHUNK - 1) g_bsum[blockIdx.x] = sh[SCAN_CHUNK - 1];
}
// scan3 with scan2 folded in: every block redundantly scans the 98 block sums
__global__ __launch_bounds__(SCAN_CHUNK)
void scan3_kernel() {
    __shared__ int sb[128];
    const int tid = threadIdx.x;
    if (tid < 128) sb[tid] = (tid < NBLK_SCAN) ? g_bsum[tid] : 0;
    __syncthreads();
#pragma unroll
    for (int off = 1; off < 128; off <<= 1) {
        int t = 0;
        if (tid < 128 && tid >= off) t = sb[tid - off];
        __syncthreads();
        if (tid < 128) sb[tid] += t;
        __syncthreads();
    }
    // exclusive offset for this block = inclusive[b] - own_sum
    const int boff = sb[blockIdx.x] - g_bsum[blockIdx.x];
    int i = blockIdx.x * SCAN_CHUNK + tid;
    if (i < NN) {
        g_off[i] += boff;
        g_dinv[i] = rsqrtf((float)g_cnt[i] + 1.0f);   // +1 self-loop
        g_cnt[i] = 0;                                  // reuse as fill cursor
    }
    if (i == 0) g_off[NN] = NE;
}
__global__ void fill_kernel(const int* __restrict__ src, const int* __restrict__ dst) {
    int e = blockIdx.x * blockDim.x + threadIdx.x;
    if (e < NE) {
        int d = dst[e];
        int p = atomicAdd(&g_cnt[d], 1);
        g_csrc[g_off[d] + p] = src[e];
    }
}

// ---------------------------------------------------------------------------
// tf32 warp-MMA GEMM1 (256 threads): g_h = X @ W1, fused with degree count
// ---------------------------------------------------------------------------
#define AS_STRIDE 36
#define BS_STRIDE 136

__device__ __forceinline__ void mma_tf32(float* c, const uint32_t* a, const uint32_t* b) {
    asm volatile(
        "mma.sync.aligned.m16n8k8.row.col.f32.tf32.tf32.f32 "
        "{%0,%1,%2,%3}, {%4,%5,%6,%7}, {%8,%9}, {%0,%1,%2,%3};"
        : "+f"(c[0]), "+f"(c[1]), "+f"(c[2]), "+f"(c[3])
        : "r"(a[0]), "r"(a[1]), "r"(a[2]), "r"(a[3]), "r"(b[0]), "r"(b[1]));
}

__device__ void gemm1_body(const float* __restrict__ Ap, const float* __restrict__ Wa,
                           int nrows, int blk) {
    __shared__ float As[128 * AS_STRIDE];
    __shared__ float Bs[32 * BS_STRIDE];

    const int tid    = threadIdx.x;
    const int lane   = tid & 31;
    const int wid    = tid >> 5;
    const int warp_m = wid >> 2;
    const int warp_n = wid & 3;
    const int rbase  = blk * 128;
    const int gid    = lane >> 2;
    const int tig    = lane & 3;

    float acc[4][4][4];
#pragma unroll
    for (int mt = 0; mt < 4; mt++)
#pragma unroll
        for (int nt = 0; nt < 4; nt++)
#pragma unroll
            for (int q = 0; q < 4; q++) acc[mt][nt][q] = 0.f;

    for (int kc = 0; kc < 128; kc += 32) {
#pragma unroll
        for (int i = 0; i < 4; i++) {
            int f   = tid + i * 256;
            int row = f >> 3;
            int c4  = (f & 7) * 4;
            float4 v = make_float4(0.f, 0.f, 0.f, 0.f);
            if (rbase + row < nrows)
                v = *reinterpret_cast<const float4*>(&Ap[(size_t)(rbase + row) * C + kc + c4]);
            uint4 w;
            w.x = f2tf32(v.x); w.y = f2tf32(v.y); w.z = f2tf32(v.z); w.w = f2tf32(v.w);
            *reinterpret_cast<uint4*>(&As[row * AS_STRIDE + c4]) = w;
        }
#pragma unroll
        for (int i = 0; i < 4; i++) {
            int f  = tid + i * 256;
            int k  = f >> 5;
            int n4 = (f & 31) * 4;
            float4 v = *reinterpret_cast<const float4*>(&Wa[(kc + k) * 128 + n4]);
            uint4 w;
            w.x = f2tf32(v.x); w.y = f2tf32(v.y); w.z = f2tf32(v.z); w.w = f2tf32(v.w);
            *reinterpret_cast<uint4*>(&Bs[k * BS_STRIDE + n4]) = w;
        }
        __syncthreads();

#pragma unroll
        for (int kk = 0; kk < 4; kk++) {
            const int k0 = kk * 8;
            uint32_t a[4][4], b[4][2];
#pragma unroll
            for (int mt = 0; mt < 4; mt++) {
                const float* p = &As[(warp_m * 64 + mt * 16 + gid) * AS_STRIDE + k0 + tig];
                a[mt][0] = __float_as_uint(p[0]);
                a[mt][1] = __float_as_uint(p[8 * AS_STRIDE]);
                a[mt][2] = __float_as_uint(p[4]);
                a[mt][3] = __float_as_uint(p[8 * AS_STRIDE + 4]);
            }
#pragma unroll
            for (int nt = 0; nt < 4; nt++) {
                const float* p = &Bs[(k0 + tig) * BS_STRIDE + warp_n * 32 + nt * 8 + gid];
                b[nt][0] = __float_as_uint(p[0]);
                b[nt][1] = __float_as_uint(p[4 * BS_STRIDE]);
            }
#pragma unroll
            for (int mt = 0; mt < 4; mt++)
#pragma unroll
                for (int nt = 0; nt < 4; nt++)
                    mma_tf32(acc[mt][nt], a[mt], b[nt]);
        }
        __syncthreads();
    }

#pragma unroll
    for (int mt = 0; mt < 4; mt++) {
        const int r0 = rbase + warp_m * 64 + mt * 16 + gid;
#pragma unroll
        for (int nt = 0; nt < 4; nt++) {
            const int col = warp_n * 32 + nt * 8 + tig * 2;
            if (r0 < nrows)
                *reinterpret_cast<float2*>(&g_h[(size_t)r0 * C + col]) =
                    make_float2(acc[mt][nt][0], acc[mt][nt][1]);
            if (r0 + 8 < nrows)
                *reinterpret_cast<float2*>(&g_h[(size_t)(r0 + 8) * C + col]) =
                    make_float2(acc[mt][nt][2], acc[mt][nt][3]);
        }
    }
}

__global__ __launch_bounds__(256, 2)
void fat_gemm1_count_kernel(const float* __restrict__ X, const float* __restrict__ W1,
                            const int* __restrict__ dst, int nrows) {
    if (blockIdx.x >= GEMM_BLOCKS) {
        int e = (blockIdx.x - GEMM_BLOCKS) * 256 + threadIdx.x;
        if (e < NE) atomicAdd(&g_cnt[dst[e]], 1);
        return;
    }
    gemm1_body(X, W1, nrows, blockIdx.x);
}

// ---------------------------------------------------------------------------
// CSR gather stage 0 (fp32): one warp per node; bias/relu/normalize -> g_hn
// ---------------------------------------------------------------------------
__global__ __launch_bounds__(256)
void gather0_kernel(const float* __restrict__ b1) {
    int node = (blockIdx.x * blockDim.x + threadIdx.x) >> 5;
    int lane = threadIdx.x & 31;
    if (node >= NN) return;

    const size_t cb = (size_t)lane * 4;
    const float dn = g_dinv[node];

    float4 hv = *reinterpret_cast<const float4*>(&g_h[(size_t)node * C + cb]);
    float cc = dn * dn;
    float4 acc = make_float4(hv.x * cc, hv.y * cc, hv.z * cc, hv.w * cc);

    int e   = g_off[node];
    int end = g_off[node + 1];

    for (; e + 8 <= end; e += 8) {
        int s[8]; float cf[8]; float4 v[8];
#pragma unroll
        for (int j = 0; j < 8; j++) s[j] = g_csrc[e + j];
#pragma unroll
        for (int j = 0; j < 8; j++) cf[j] = g_dinv[s[j]] * dn;
#pragma unroll
        for (int j = 0; j < 8; j++)
            v[j] = *reinterpret_cast<const float4*>(&g_h[(size_t)s[j] * C + cb]);
#pragma unroll
        for (int j = 0; j < 8; j++) {
            acc.x = fmaf(cf[j], v[j].x, acc.x);
            acc.y = fmaf(cf[j], v[j].y, acc.y);
            acc.z = fmaf(cf[j], v[j].z, acc.z);
            acc.w = fmaf(cf[j], v[j].w, acc.w);
        }
    }
    for (; e < end; e++) {
        int s = g_csrc[e];
        float c = g_dinv[s] * dn;
        float4 v = *reinterpret_cast<const float4*>(&g_h[(size_t)s * C + cb]);
        acc.x = fmaf(c, v.x, acc.x);
        acc.y = fmaf(c, v.y, acc.y);
        acc.z = fmaf(c, v.z, acc.z);
        acc.w = fmaf(c, v.w, acc.w);
    }

    float4 bv = *reinterpret_cast<const float4*>(&b1[cb]);
    acc.x = fmaxf(acc.x + bv.x, 0.f);
    acc.y = fmaxf(acc.y + bv.y, 0.f);
    acc.z = fmaxf(acc.z + bv.z, 0.f);
    acc.w = fmaxf(acc.w + bv.w, 0.f);
    float ss = acc.x * acc.x + acc.y * acc.y + acc.z * acc.z + acc.w * acc.w;
#pragma unroll
    for (int off = 16; off > 0; off >>= 1)
        ss += __shfl_xor_sync(0xffffffffu, ss, off);
    float scale = 1.0f / fmaxf(sqrtf(ss), 1e-12f);
    acc.x *= scale; acc.y *= scale; acc.z *= scale; acc.w *= scale;
    *reinterpret_cast<float4*>(&g_hn[(size_t)node * C + cb]) = acc;
}

// ---------------------------------------------------------------------------
// Fused gather1 + final GEMM (512 threads):
//   phase 1: 16 warps gather 128 nodes' aggregates of g_hn -> smem Vs (tf32)
//   phase 2: [mu|logstd] = Vs @ [Wmu|Wls] + bias -> out
// ---------------------------------------------------------------------------
#define VS_STRIDE 132
#define FUSED_SMEM ((128 * VS_STRIDE + 32 * BS_STRIDE) * 4)   // 84992 B

__global__ __launch_bounds__(512, 2)
void fused_gather_gemm_kernel(const float* __restrict__ Wmu, const float* __restrict__ Wls,
                              const float* __restrict__ bmu, const float* __restrict__ bls,
                              float* __restrict__ out, int nrows) {
    extern __shared__ float sm[];
    float* Vs = sm;                        // [128][VS_STRIDE]
    float* Bs = sm + 128 * VS_STRIDE;      // [32][BS_STRIDE]

    const int tid  = threadIdx.x;
    const int lane = tid & 31;
    const int wid  = tid >> 5;             // 0..15
    const int rbase = blockIdx.x * 128;

    // ---- phase 1: gather (warp per node, 8 nodes per warp) ----
    {
        const size_t cb = (size_t)lane * 4;
        for (int it = 0; it < 8; it++) {
            const int nl = it * 16 + wid;
            const int node = rbase + nl;
            float4 acc = make_float4(0.f, 0.f, 0.f, 0.f);
            if (node < nrows) {
                const float dn = g_dinv[node];
                float4 hv = *reinterpret_cast<const float4*>(&g_hn[(size_t)node * C + cb]);
                float cc = dn * dn;
                acc = make_float4(hv.x * cc, hv.y * cc, hv.z * cc, hv.w * cc);
                int e   = g_off[node];
                int end = g_off[node + 1];
                for (; e + 4 <= end; e += 4) {
                    int s[4]; float cf[4]; float4 v[4];
#pragma unroll
                    for (int j = 0; j < 4; j++) s[j] = g_csrc[e + j];
#pragma unroll
                    for (int j = 0; j < 4; j++) cf[j] = g_dinv[s[j]] * dn;
#pragma unroll
                    for (int j = 0; j < 4; j++)
                        v[j] = *reinterpret_cast<const float4*>(&g_hn[(size_t)s[j] * C + cb]);
#pragma unroll
                    for (int j = 0; j < 4; j++) {
                        acc.x = fmaf(cf[j], v[j].x, acc.x);
                        acc.y = fmaf(cf[j], v[j].y, acc.y);
                        acc.z = fmaf(cf[j], v[j].z, acc.z);
                        acc.w = fmaf(cf[j], v[j].w, acc.w);
                    }
                }
                for (; e < end; e++) {
                    int s = g_csrc[e];
                    float c = g_dinv[s] * dn;
                    float4 v = *reinterpret_cast<const float4*>(&g_hn[(size_t)s * C + cb]);
                    acc.x = fmaf(c, v.x, acc.x);
                    acc.y = fmaf(c, v.y, acc.y);
                    acc.z = fmaf(c, v.z, acc.z);
                    acc.w = fmaf(c, v.w, acc.w);
                }
            }
            uint4 w;
            w.x = f2tf32(acc.x); w.y = f2tf32(acc.y);
            w.z = f2tf32(acc.z); w.w = f2tf32(acc.w);
            *reinterpret_cast<uint4*>(&Vs[nl * VS_STRIDE + lane * 4]) = w;
        }
    }
    __syncthreads();

    // ---- phase 2: GEMM from smem (16 warps: 4x4, warp tile 32x32) ----
    const int warp_m = wid >> 2;
    const int warp_n = wid & 3;
    const int gid    = lane >> 2;
    const int tig    = lane & 3;

    float acc[2][4][4];
#pragma unroll
    for (int mt = 0; mt < 2; mt++)
#pragma unroll
        for (int nt = 0; nt < 4; nt++)
#pragma unroll
            for (int q = 0; q < 4; q++) acc[mt][nt][q] = 0.f;

    for (int kc = 0; kc < 128; kc += 32) {
#pragma unroll
        for (int i = 0; i < 2; i++) {
            int f  = tid + i * 512;
            int k  = f >> 5;
            int n4 = (f & 31) * 4;
            float4 v = (n4 < 64)
                ? *reinterpret_cast<const float4*>(&Wmu[(kc + k) * 64 + n4])
                : *reinterpret_cast<const float4*>(&Wls[(kc + k) * 64 + n4 - 64]);
            uint4 w;
            w.x = f2tf32(v.x); w.y = f2tf32(v.y); w.z = f2tf32(v.z); w.w = f2tf32(v.w);
            *reinterpret_cast<uint4*>(&Bs[k * BS_STRIDE + n4]) = w;
        }
        __syncthreads();

#pragma unroll
        for (int kk = 0; kk < 4; kk++) {
            const int k0 = kk * 8;
            uint32_t a[2][4], b[4][2];
#pragma unroll
            for (int mt = 0; mt < 2; mt++) {
                const float* p = &Vs[(warp_m * 32 + mt * 16 + gid) * VS_STRIDE + kc + k0 + tig];
                a[mt][0] = __float_as_uint(p[0]);
                a[mt][1] = __float_as_uint(p[8 * VS_STRIDE]);
                a[mt][2] = __float_as_uint(p[4]);
                a[mt][3] = __float_as_uint(p[8 * VS_STRIDE + 4]);
            }
#pragma unroll
            for (int nt = 0; nt < 4; nt++) {
                const float* p = &Bs[(k0 + tig) * BS_STRIDE + warp_n * 32 + nt * 8 + gid];
                b[nt][0] = __float_as_uint(p[0]);
                b[nt][1] = __float_as_uint(p[4 * BS_STRIDE]);
            }
#pragma unroll
            for (int mt = 0; mt < 2; mt++)
#pragma unroll
                for (int nt = 0; nt < 4; nt++)
                    mma_tf32(acc[mt][nt], a[mt], b[nt]);
        }
        __syncthreads();
    }

#pragma unroll
    for (int mt = 0; mt < 2; mt++) {
        const int r0 = rbase + warp_m * 32 + mt * 16 + gid;
#pragma unroll
        for (int nt = 0; nt < 4; nt++) {
            const int col = warp_n * 32 + nt * 8 + tig * 2;
            const bool is_mu = (col < 64);
            const int  jo    = is_mu ? col : col - 64;
            const float* bp  = is_mu ? bmu : bls;
            float* obase     = is_mu ? out : out + (size_t)NN * 64;
            float2 bv = *reinterpret_cast<const float2*>(&bp[jo]);
            if (r0 < nrows)
                *reinterpret_cast<float2*>(&obase[(size_t)r0 * 64 + jo]) =
                    make_float2(acc[mt][nt][0] + bv.x, acc[mt][nt][1] + bv.y);
            if (r0 + 8 < nrows)
                *reinterpret_cast<float2*>(&obase[(size_t)(r0 + 8) * 64 + jo]) =
                    make_float2(acc[mt][nt][2] + bv.x, acc[mt][nt][3] + bv.y);
        }
    }
}

// ---------------------------------------------------------------------------
extern "C" void kernel_launch(void* const* d_in, const int* in_sizes, int n_in,
                              void* d_out, int out_size) {
    const float* x   = (const float*)d_in[0];
    const int*   ei  = (const int*)  d_in[1];
    const float* W1  = (const float*)d_in[2];
    const float* b1  = (const float*)d_in[3];
    const float* Wmu = (const float*)d_in[4];
    const float* bmu = (const float*)d_in[5];
    const float* Wls = (const float*)d_in[6];
    const float* bls = (const float*)d_in[7];
    float* out = (float*)d_out;

    const int* src = ei;
    const int* dst = ei + NE;

    const int gather_blocks = (NN * 32 + 255) / 256;  // 12500

    cudaFuncSetAttribute(fused_gather_gemm_kernel,
                         cudaFuncAttributeMaxDynamicSharedMemorySize, FUSED_SMEM);

    zero_cnt_kernel<<<(NN + 255) / 256, 256>>>();
    fat_gemm1_count_kernel<<<GEMM_BLOCKS + COUNT_BLOCKS, 256>>>(x, W1, dst, NN);
    scan1_kernel<<<NBLK_SCAN, SCAN_CHUNK>>>();
    scan3_kernel<<<NBLK_SCAN, SCAN_CHUNK>>>();
    fill_kernel<<<COUNT_BLOCKS, 256>>>(src, dst);
    gather0_kernel<<<gather_blocks, 256>>>(b1);
    fused_gather_gemm_kernel<<<GEMM_BLOCKS, 512, FUSED_SMEM>>>(Wmu, Wls, bmu, bls, out, NN);
}

// round 11
// speedup vs baseline: 1.5355x; 1.5355x over previous
#include <cuda_runtime.h>
#include <cstdint>

#define NN 100000
#define NE 1600000
#define C  128

#define GEMM_BLOCKS  ((NN + 127) / 128)    // 782
#define EDGE_BLOCKS  ((NE + 255) / 256)    // 6250

#define SCAN_CHUNK 1024
#define NBLK_SCAN ((NN + SCAN_CHUNK - 1) / SCAN_CHUNK)   // 98

// ---------------------------------------------------------------------------
// Scratch (device globals — no allocation allowed)
// ---------------------------------------------------------------------------
__device__ int   g_cnt [NN];
__device__ int   g_off [NN + 1];
__device__ int   g_bsum[SCAN_CHUNK];
__device__ int   g_csrc[NE];
__device__ float g_dinv[NN];
__device__ float g_h   [(size_t)NN * C];   // x@W1 (fp32)
__device__ float g_hn  [(size_t)NN * C];   // normalized hidden (fp32)
__device__ float g_agg2[(size_t)NN * C];   // stage-2 aggregate (tf32-rounded fp32)

__device__ __forceinline__ uint32_t f2tf32(float f) {
    uint32_t r; asm("cvt.rna.tf32.f32 %0, %1;" : "=r"(r) : "f"(f)); return r;
}

// ---------------------------------------------------------------------------
// CSR build pieces (run on side stream, overlapped with GEMM1)
// ---------------------------------------------------------------------------
__global__ void count_kernel(const int* __restrict__ dst) {
    int e = blockIdx.x * blockDim.x + threadIdx.x;
    if (e < NE) atomicAdd(&g_cnt[dst[e]], 1);
}
__global__ __launch_bounds__(SCAN_CHUNK)
void scan1_kernel() {
    __shared__ int sh[SCAN_CHUNK];
    int i = blockIdx.x * SCAN_CHUNK + threadIdx.x;
    int v = (i < NN) ? g_cnt[i] : 0;
    sh[threadIdx.x] = v;
    __syncthreads();
#pragma unroll
    for (int off = 1; off < SCAN_CHUNK; off <<= 1) {
        int t = (threadIdx.x >= off) ? sh[threadIdx.x - off] : 0;
        __syncthreads();
        sh[threadIdx.x] += t;
        __syncthreads();
    }
    if (i < NN) g_off[i] = sh[threadIdx.x] - v;   // exclusive within block
    if (threadIdx.x == SCAN_CHUNK - 1) g_bsum[blockIdx.x] = sh[SCAN_CHUNK - 1];
}
// scan3 with scan2 folded in: every block redundantly scans the 98 block sums
__global__ __launch_bounds__(SCAN_CHUNK)
void scan3_kernel() {
    __shared__ int sb[128];
    const int tid = threadIdx.x;
    if (tid < 128) sb[tid] = (tid < NBLK_SCAN) ? g_bsum[tid] : 0;
    __syncthreads();
#pragma unroll
    for (int off = 1; off < 128; off <<= 1) {
        int t = 0;
        if (tid < 128 && tid >= off) t = sb[tid - off];
        __syncthreads();
        if (tid < 128) sb[tid] += t;
        __syncthreads();
    }
    const int boff = sb[blockIdx.x] - g_bsum[blockIdx.x];
    int i = blockIdx.x * SCAN_CHUNK + tid;
    if (i < NN) {
        g_off[i] += boff;
        g_dinv[i] = rsqrtf((float)g_cnt[i] + 1.0f);   // +1 self-loop
        g_cnt[i] = 0;                                  // reuse as fill cursor
    }
    if (i == 0) g_off[NN] = NE;
}
__global__ void fill_kernel(const int* __restrict__ src, const int* __restrict__ dst) {
    int e = blockIdx.x * blockDim.x + threadIdx.x;
    if (e < NE) {
        int d = dst[e];
        int p = atomicAdd(&g_cnt[d], 1);
        g_csrc[g_off[d] + p] = src[e];
    }
}

// ---------------------------------------------------------------------------
// tf32 warp-MMA GEMM
// ---------------------------------------------------------------------------
#define AS_STRIDE 36
#define BS_STRIDE 136

__device__ __forceinline__ void mma_tf32(float* c, const uint32_t* a, const uint32_t* b) {
    asm volatile(
        "mma.sync.aligned.m16n8k8.row.col.f32.tf32.tf32.f32 "
        "{%0,%1,%2,%3}, {%4,%5,%6,%7}, {%8,%9}, {%0,%1,%2,%3};"
        : "+f"(c[0]), "+f"(c[1]), "+f"(c[2]), "+f"(c[3])
        : "r"(a[0]), "r"(a[1]), "r"(a[2]), "r"(a[3]), "r"(b[0]), "r"(b[1]));
}

// MODE 0: A = X (cvt to tf32), W = W1 [128,128]  -> g_h
// MODE 1: A = g_agg2 (pre-rounded), W = [Wmu|Wls] -> out + bias
template <int MODE>
__device__ void gemm_body(const float* __restrict__ Ap,
                          const float* __restrict__ Wa, const float* __restrict__ Wb,
                          const float* __restrict__ bmu, const float* __restrict__ bls,
                          float* __restrict__ out, int nrows, int blk) {
    __shared__ float As[128 * AS_STRIDE];
    __shared__ float Bs[32 * BS_STRIDE];

    const int tid    = threadIdx.x;
    const int lane   = tid & 31;
    const int wid    = tid >> 5;
    const int warp_m = wid >> 2;
    const int warp_n = wid & 3;
    const int rbase  = blk * 128;
    const int gid    = lane >> 2;
    const int tig    = lane & 3;

    float acc[4][4][4];
#pragma unroll
    for (int mt = 0; mt < 4; mt++)
#pragma unroll
        for (int nt = 0; nt < 4; nt++)
#pragma unroll
            for (int q = 0; q < 4; q++) acc[mt][nt][q] = 0.f;

    for (int kc = 0; kc < 128; kc += 32) {
#pragma unroll
        for (int i = 0; i < 4; i++) {
            int f   = tid + i * 256;
            int row = f >> 3;
            int c4  = (f & 7) * 4;
            float4 v = make_float4(0.f, 0.f, 0.f, 0.f);
            if (rbase + row < nrows)
                v = *reinterpret_cast<const float4*>(&Ap[(size_t)(rbase + row) * C + kc + c4]);
            if (MODE == 0) {
                uint4 w;
                w.x = f2tf32(v.x); w.y = f2tf32(v.y); w.z = f2tf32(v.z); w.w = f2tf32(v.w);
                *reinterpret_cast<uint4*>(&As[row * AS_STRIDE + c4]) = w;
            } else {
                *reinterpret_cast<float4*>(&As[row * AS_STRIDE + c4]) = v;  // pre-rounded
            }
        }
#pragma unroll
        for (int i = 0; i < 4; i++) {
            int f  = tid + i * 256;
            int k  = f >> 5;
            int n4 = (f & 31) * 4;
            float4 v;
            if (MODE == 0) {
                v = *reinterpret_cast<const float4*>(&Wa[(kc + k) * 128 + n4]);
            } else {
                v = (n4 < 64)
                    ? *reinterpret_cast<const float4*>(&Wa[(kc + k) * 64 + n4])
                    : *reinterpret_cast<const float4*>(&Wb[(kc + k) * 64 + n4 - 64]);
            }
            uint4 w;
            w.x = f2tf32(v.x); w.y = f2tf32(v.y); w.z = f2tf32(v.z); w.w = f2tf32(v.w);
            *reinterpret_cast<uint4*>(&Bs[k * BS_STRIDE + n4]) = w;
        }
        __syncthreads();

#pragma unroll
        for (int kk = 0; kk < 4; kk++) {
            const int k0 = kk * 8;
            uint32_t a[4][4], b[4][2];
#pragma unroll
            for (int mt = 0; mt < 4; mt++) {
                const float* p = &As[(warp_m * 64 + mt * 16 + gid) * AS_STRIDE + k0 + tig];
                a[mt][0] = __float_as_uint(p[0]);
                a[mt][1] = __float_as_uint(p[8 * AS_STRIDE]);
                a[mt][2] = __float_as_uint(p[4]);
                a[mt][3] = __float_as_uint(p[8 * AS_STRIDE + 4]);
            }
#pragma unroll
            for (int nt = 0; nt < 4; nt++) {
                const float* p = &Bs[(k0 + tig) * BS_STRIDE + warp_n * 32 + nt * 8 + gid];
                b[nt][0] = __float_as_uint(p[0]);
                b[nt][1] = __float_as_uint(p[4 * BS_STRIDE]);
            }
#pragma unroll
            for (int mt = 0; mt < 4; mt++)
#pragma unroll
                for (int nt = 0; nt < 4; nt++)
                    mma_tf32(acc[mt][nt], a[mt], b[nt]);
        }
        __syncthreads();
    }

#pragma unroll
    for (int mt = 0; mt < 4; mt++) {
        const int r0 = rbase + warp_m * 64 + mt * 16 + gid;
#pragma unroll
        for (int nt = 0; nt < 4; nt++) {
            const int col = warp_n * 32 + nt * 8 + tig * 2;
            if (MODE == 0) {
                if (r0 < nrows)
                    *reinterpret_cast<float2*>(&g_h[(size_t)r0 * C + col]) =
                        make_float2(acc[mt][nt][0], acc[mt][nt][1]);
                if (r0 + 8 < nrows)
                    *reinterpret_cast<float2*>(&g_h[(size_t)(r0 + 8) * C + col]) =
                        make_float2(acc[mt][nt][2], acc[mt][nt][3]);
            } else {
                const bool is_mu = (col < 64);
                const int  jo    = is_mu ? col : col - 64;
                const float* bp  = is_mu ? bmu : bls;
                float* obase     = is_mu ? out : out + (size_t)NN * 64;
                float2 bv = *reinterpret_cast<const float2*>(&bp[jo]);
                if (r0 < nrows)
                    *reinterpret_cast<float2*>(&obase[(size_t)r0 * 64 + jo]) =
                        make_float2(acc[mt][nt][0] + bv.x, acc[mt][nt][1] + bv.y);
                if (r0 + 8 < nrows)
                    *reinterpret_cast<float2*>(&obase[(size_t)(r0 + 8) * 64 + jo]) =
                        make_float2(acc[mt][nt][2] + bv.x, acc[mt][nt][3] + bv.y);
            }
        }
    }
}

__global__ __launch_bounds__(256, 2)
void gemm1_kernel(const float* __restrict__ X, const float* __restrict__ W1, int nrows) {
    gemm_body<0>(X, W1, nullptr, nullptr, nullptr, nullptr, nrows, blockIdx.x);
}

__global__ __launch_bounds__(256, 2)
void gemm_final_kernel(const float* __restrict__ Wmu, const float* __restrict__ Wls,
                       const float* __restrict__ bmu, const float* __restrict__ bls,
                       float* __restrict__ out, int nrows) {
    gemm_body<1>(g_agg2, Wmu, Wls, bmu, bls, out, nrows, blockIdx.x);
}

// ---------------------------------------------------------------------------
// CSR gather (fp32): one warp per node, lane owns 4 channels; 8-deep MLP batch.
// STAGE 0: H=g_h  -> bias/relu/normalize -> g_hn
// STAGE 1: H=g_hn -> g_agg2 (tf32-rounded)
// ---------------------------------------------------------------------------
template <int STAGE>
__global__ __launch_bounds__(256)
void gather_kernel(const float* __restrict__ b1) {
    int node = (blockIdx.x * blockDim.x + threadIdx.x) >> 5;
    int lane = threadIdx.x & 31;
    if (node >= NN) return;

    const float* __restrict__ H = (STAGE == 0) ? g_h : g_hn;
    const size_t cb = (size_t)lane * 4;
    const float dn = g_dinv[node];

    float4 hv = *reinterpret_cast<const float4*>(&H[(size_t)node * C + cb]);
    float cc = dn * dn;
    float4 acc = make_float4(hv.x * cc, hv.y * cc, hv.z * cc, hv.w * cc);

    int e   = g_off[node];
    int end = g_off[node + 1];

    for (; e + 8 <= end; e += 8) {
        int s[8]; float cf[8]; float4 v[8];
#pragma unroll
        for (int j = 0; j < 8; j++) s[j] = g_csrc[e + j];
#pragma unroll
        for (int j = 0; j < 8; j++) cf[j] = g_dinv[s[j]] * dn;
#pragma unroll
        for (int j = 0; j < 8; j++)
            v[j] = *reinterpret_cast<const float4*>(&H[(size_t)s[j] * C + cb]);
#pragma unroll
        for (int j = 0; j < 8; j++) {
            acc.x = fmaf(cf[j], v[j].x, acc.x);
            acc.y = fmaf(cf[j], v[j].y, acc.y);
            acc.z = fmaf(cf[j], v[j].z, acc.z);
            acc.w = fmaf(cf[j], v[j].w, acc.w);
        }
    }
    if (e + 4 <= end) {
        int s[4]; float cf[4]; float4 v[4];
#pragma unroll
        for (int j = 0; j < 4; j++) s[j] = g_csrc[e + j];
#pragma unroll
        for (int j = 0; j < 4; j++) cf[j] = g_dinv[s[j]] * dn;
#pragma unroll
        for (int j = 0; j < 4; j++)
            v[j] = *reinterpret_cast<const float4*>(&H[(size_t)s[j] * C + cb]);
#pragma unroll
        for (int j = 0; j < 4; j++) {
            acc.x = fmaf(cf[j], v[j].x, acc.x);
            acc.y = fmaf(cf[j], v[j].y, acc.y);
            acc.z = fmaf(cf[j], v[j].z, acc.z);
            acc.w = fmaf(cf[j], v[j].w, acc.w);
        }
        e += 4;
    }
    for (; e < end; e++) {
        int s = g_csrc[e];
        float c = g_dinv[s] * dn;
        float4 v = *reinterpret_cast<const float4*>(&H[(size_t)s * C + cb]);
        acc.x = fmaf(c, v.x, acc.x);
        acc.y = fmaf(c, v.y, acc.y);
        acc.z = fmaf(c, v.z, acc.z);
        acc.w = fmaf(c, v.w, acc.w);
    }

    if (STAGE == 0) {
        float4 bv = *reinterpret_cast<const float4*>(&b1[cb]);
        acc.x = fmaxf(acc.x + bv.x, 0.f);
        acc.y = fmaxf(acc.y + bv.y, 0.f);
        acc.z = fmaxf(acc.z + bv.z, 0.f);
        acc.w = fmaxf(acc.w + bv.w, 0.f);
        float ss = acc.x * acc.x + acc.y * acc.y + acc.z * acc.z + acc.w * acc.w;
#pragma unroll
        for (int off = 16; off > 0; off >>= 1)
            ss += __shfl_xor_sync(0xffffffffu, ss, off);
        float scale = 1.0f / fmaxf(sqrtf(ss), 1e-12f);
        acc.x *= scale; acc.y *= scale; acc.z *= scale; acc.w *= scale;
        *reinterpret_cast<float4*>(&g_hn[(size_t)node * C + cb]) = acc;
    } else {
        uint4 w;
        w.x = f2tf32(acc.x); w.y = f2tf32(acc.y);
        w.z = f2tf32(acc.z); w.w = f2tf32(acc.w);
        *reinterpret_cast<uint4*>(&g_agg2[(size_t)node * C + cb]) = w;
    }
}

// ---------------------------------------------------------------------------
extern "C" void kernel_launch(void* const* d_in, const int* in_sizes, int n_in,
                              void* d_out, int out_size) {
    const float* x   = (const float*)d_in[0];
    const int*   ei  = (const int*)  d_in[1];
    const float* W1  = (const float*)d_in[2];
    const float* b1  = (const float*)d_in[3];
    const float* Wmu = (const float*)d_in[4];
    const float* bmu = (const float*)d_in[5];
    const float* Wls = (const float*)d_in[6];
    const float* bls = (const float*)d_in[7];
    float* out = (float*)d_out;

    const int* src = ei;
    const int* dst = ei + NE;

    const int gather_blocks = (NN * 32 + 255) / 256;  // 12500

    // One-time setup (first call is the non-captured correctness run)
    static cudaStream_t s2 = nullptr;
    static cudaEvent_t  evF = nullptr, evJ = nullptr;
    static void* cnt_ptr = nullptr;
    if (s2 == nullptr) {
        cudaStreamCreateWithFlags(&s2, cudaStreamNonBlocking);
        cudaEventCreateWithFlags(&evF, cudaEventDisableTiming);
        cudaEventCreateWithFlags(&evJ, cudaEventDisableTiming);
        cudaGetSymbolAddress(&cnt_ptr, g_cnt);
    }

    // main stream: zero counts, then fork
    cudaMemsetAsync(cnt_ptr, 0, NN * sizeof(int), 0);
    cudaEventRecord(evF, 0);
    cudaStreamWaitEvent(s2, evF, 0);

    // side stream: CSR chain (count -> scan -> fill)
    count_kernel<<<EDGE_BLOCKS, 256, 0, s2>>>(dst);
    scan1_kernel<<<NBLK_SCAN, SCAN_CHUNK, 0, s2>>>();
    scan3_kernel<<<NBLK_SCAN, SCAN_CHUNK, 0, s2>>>();
    fill_kernel<<<EDGE_BLOCKS, 256, 0, s2>>>(src, dst);
    cudaEventRecord(evJ, s2);

    // main stream: GEMM1 runs concurrently with the CSR chain
    gemm1_kernel<<<GEMM_BLOCKS, 256>>>(x, W1, NN);

    // join, then the serial tail
    cudaStreamWaitEvent(0, evJ, 0);
    gather_kernel<0><<<gather_blocks, 256>>>(b1);
    gather_kernel<1><<<gather_blocks, 256>>>(b1);
    gemm_final_kernel<<<GEMM_BLOCKS, 256>>>(Wmu, Wls, bmu, bls, out, NN);
}